// round 2
// baseline (speedup 1.0000x reference)
#include <cuda_runtime.h>
#include <math.h>

#define Bsz 2
#define Lsz 1024
#define DM 512
#define DSTATE 16
#define HD 64
#define DI 1024
#define NH 16
#define NL 6
#define FFND 2048
#define CONVD 1056
#define DPROJ 2096
#define ROWS (Bsz*Lsz)   // 2048

// ---------------- scratch (static __device__, no allocation) ----------------
__device__ float g_xbuf[ROWS*DM];          // residual stream x
__device__ float g_s[ROWS*DM];             // rms output / ffn hidden input
__device__ float g_zx[2][ROWS*DPROJ];      // in_proj output per direction
__device__ float g_xconv[2][ROWS*CONVD];   // conv+silu output per direction
__device__ float g_dt[2][ROWS*NH];
__device__ float g_dA[2][ROWS*NH];
__device__ float g_y[2][ROWS*DI];          // scan output (+D*x)
__device__ float g_gbuf[ROWS*2*DI];        // gated-normed, [row][dir*1024+j]
__device__ float g_ffnh[ROWS*FFND];

__device__ __forceinline__ float siluf(float x){ return x / (1.0f + expf(-x)); }
__device__ __forceinline__ float gelunf(float x){ return 0.5f*x*(1.0f+erff(x*0.70710678118654752f)); }

// ---------------- simple copy ----------------
__global__ void copy_k(const float* __restrict__ in, float* __restrict__ out, int n){
    int i = blockIdx.x*blockDim.x + threadIdx.x;
    if (i < n) out[i] = in[i];
}

// ---------------- RMSNorm over 512 dims; optional (+pos)*mask ----------------
__global__ void rms512_k(const float* __restrict__ in, const float* __restrict__ w,
                         const float* __restrict__ pos, const float* __restrict__ mask,
                         float* __restrict__ out, float eps)
{
    int row = blockIdx.x;
    int tid = threadIdx.x;  // 128 threads, float4 each = 512
    const float4 v = ((const float4*)(in + (size_t)row*DM))[tid];
    float ss = v.x*v.x + v.y*v.y + v.z*v.z + v.w*v.w;
    #pragma unroll
    for (int o = 16; o > 0; o >>= 1) ss += __shfl_xor_sync(0xffffffffu, ss, o);
    __shared__ float ws[4];
    if ((tid & 31) == 0) ws[tid >> 5] = ss;
    __syncthreads();
    float tot = ws[0] + ws[1] + ws[2] + ws[3];
    float inv = rsqrtf(tot * (1.0f/DM) + eps);
    const float4 wv = ((const float4*)w)[tid];
    float4 o4;
    o4.x = v.x*inv*wv.x; o4.y = v.y*inv*wv.y; o4.z = v.z*inv*wv.z; o4.w = v.w*inv*wv.w;
    if (pos){
        float m = mask[row];
        const float4 p4 = ((const float4*)(pos + (size_t)row*DM))[tid];
        o4.x = (o4.x + p4.x)*m; o4.y = (o4.y + p4.y)*m;
        o4.z = (o4.z + p4.z)*m; o4.w = (o4.w + p4.w)*m;
    }
    ((float4*)(out + (size_t)row*DM))[tid] = o4;
}

// ---------------- SGEMM 128x128x8, 256 thr, 8x8 per thread ----------------
// EPI 0: C = acc
// EPI 1: C = gelu(acc + bias[col])
// EPI 2: C = C + acc + bias[col]          (ffn2 residual, in-place)
// EPI 3: C += scale * extra[row] * acc    (out-proj combine into residual)
template<int EPI>
__global__ __launch_bounds__(256)
void sgemm_k(const float* __restrict__ A, const float* __restrict__ B,
             float* __restrict__ C, int M, int N, int K,
             const float* __restrict__ bias, const float* __restrict__ extra,
             float scale, long strideB, long strideC)
{
    B += (size_t)blockIdx.z * strideB;
    C += (size_t)blockIdx.z * strideC;
    __shared__ float As[8][128];
    __shared__ float Bs[8][128];
    const int tid = threadIdx.x;
    const int bx = blockIdx.x, by = blockIdx.y;
    const int arow = tid >> 1, acol = (tid & 1)*4;
    const int brow = tid >> 5, bcol = (tid & 31)*4;
    const int gcolB = bx*128 + bcol;
    const float* Aptr = A + (size_t)(by*128 + arow)*K + acol;
    const float* Bptr = B + (size_t)brow*N + gcolB;
    const bool bok = (gcolB < N);
    float acc[8][8];
    #pragma unroll
    for (int i = 0; i < 8; i++)
        #pragma unroll
        for (int j = 0; j < 8; j++) acc[i][j] = 0.f;
    const int ty = tid >> 4, tx = tid & 15;

    for (int k0 = 0; k0 < K; k0 += 8){
        float4 a4 = *(const float4*)Aptr;
        float4 b4 = make_float4(0.f,0.f,0.f,0.f);
        if (bok) b4 = *(const float4*)Bptr;
        Aptr += 8; Bptr += (size_t)8*N;
        As[acol+0][arow] = a4.x; As[acol+1][arow] = a4.y;
        As[acol+2][arow] = a4.z; As[acol+3][arow] = a4.w;
        *(float4*)&Bs[brow][bcol] = b4;
        __syncthreads();
        #pragma unroll
        for (int kk = 0; kk < 8; kk++){
            float ra[8], rb[8];
            *(float4*)&ra[0] = *(const float4*)&As[kk][ty*8];
            *(float4*)&ra[4] = *(const float4*)&As[kk][ty*8+4];
            *(float4*)&rb[0] = *(const float4*)&Bs[kk][tx*8];
            *(float4*)&rb[4] = *(const float4*)&Bs[kk][tx*8+4];
            #pragma unroll
            for (int i = 0; i < 8; i++)
                #pragma unroll
                for (int j = 0; j < 8; j++)
                    acc[i][j] = fmaf(ra[i], rb[j], acc[i][j]);
        }
        __syncthreads();
    }

    const int row0 = by*128 + ty*8, col0 = bx*128 + tx*8;
    #pragma unroll
    for (int i = 0; i < 8; i++){
        const size_t r = (size_t)(row0 + i);
        float m = 0.f;
        if (EPI == 3) m = scale * extra[r];
        #pragma unroll
        for (int j = 0; j < 8; j++){
            int c = col0 + j;
            if (c < N){
                float v = acc[i][j];
                if (EPI == 0)      C[r*N + c] = v;
                else if (EPI == 1) C[r*N + c] = gelunf(v + bias[c]);
                else if (EPI == 2) C[r*N + c] = C[r*N + c] + v + bias[c];
                else if (EPI == 3) C[r*N + c] = fmaf(m, v, C[r*N + c]);
            }
        }
    }
}

// ---------------- causal depthwise conv (dir-aware) + SiLU ----------------
__global__ void conv_k(const float* __restrict__ cw, const float* __restrict__ cb)
{
    const int dir = blockIdx.y;
    const int idx = blockIdx.x*blockDim.x + threadIdx.x;
    if (idx >= ROWS*CONVD) return;
    const int row = idx / CONVD, c = idx - row*CONVD;
    const int b = row >> 10, l = row & 1023;
    const float* zx = g_zx[dir];
    const float* w = cw + (size_t)dir*CONVD*4 + (size_t)c*4;
    float acc = cb[dir*CONVD + c];
    #pragma unroll
    for (int k = 0; k < 4; k++){
        int lp = dir ? (l + 3 - k) : (l - 3 + k);
        if (lp >= 0 && lp < Lsz)
            acc = fmaf(w[k], zx[(size_t)(b*Lsz + lp)*DPROJ + DI + c], acc);
    }
    g_xconv[dir][idx] = siluf(acc);
}

// ---------------- dt = softplus(raw + bias); dA = exp(dt * -exp(A_log)) ----
__global__ void dt_k(const float* __restrict__ dtb, const float* __restrict__ Alog)
{
    const int dir = blockIdx.y;
    const int idx = blockIdx.x*blockDim.x + threadIdx.x;
    if (idx >= ROWS*NH) return;
    const int row = idx >> 4, h = idx & 15;
    float raw = g_zx[dir][(size_t)row*DPROJ + DI + CONVD + h] + dtb[dir*NH + h];
    float dt = (raw > 20.f) ? raw : log1pf(expf(raw));
    float A = -expf(Alog[dir*NH + h]);
    g_dt[dir][idx] = dt;
    g_dA[dir][idx] = expf(dt * A);
}

// ---------------- selective scan: block per (dir,b,head), thread per p ------
__global__ __launch_bounds__(64)
void scan_k(const float* __restrict__ Dvec)
{
    const int blk = blockIdx.x;
    const int dir = blk >> 5, b = (blk >> 4) & 1, h = blk & 15;
    const float* xc  = g_xconv[dir];
    const float* dtp = g_dt[dir];
    const float* dAp = g_dA[dir];
    float* yp = g_y[dir];
    const float Dh = Dvec[dir*NH + h];
    const int p = threadIdx.x;
    const int base = b*Lsz;

    __shared__ float sX[64][64];
    __shared__ float sB[64][16], sC[64][16];
    __shared__ float sdA[64], sdt[64];

    float hreg[16];
    #pragma unroll
    for (int j = 0; j < 16; j++) hreg[j] = 0.f;

    for (int t0 = 0; t0 < Lsz; t0 += 64){
        // stage x chunk (64 t x 64 p)
        #pragma unroll
        for (int i = 0; i < 16; i++){
            int li = p + i*64;
            int tl = li >> 4, pq = li & 15;
            int grow = base + (dir ? (Lsz-1 - (t0+tl)) : (t0+tl));
            *(float4*)&sX[tl][pq*4] =
                *(const float4*)&xc[(size_t)grow*CONVD + h*HD + pq*4];
        }
        // stage B,C (64 t x 16 n)
        #pragma unroll
        for (int i = 0; i < 4; i++){
            int li = p + i*64;
            int tl = li >> 2, j4 = (li & 3)*4;
            int grow = base + (dir ? (Lsz-1 - (t0+tl)) : (t0+tl));
            *(float4*)&sB[tl][j4] = *(const float4*)&xc[(size_t)grow*CONVD + DI + j4];
            *(float4*)&sC[tl][j4] = *(const float4*)&xc[(size_t)grow*CONVD + DI + DSTATE + j4];
        }
        {
            int grow = base + (dir ? (Lsz-1 - (t0+p)) : (t0+p));
            sdA[p] = dAp[grow*NH + h];
            sdt[p] = dtp[grow*NH + h];
        }
        __syncthreads();

        for (int tl = 0; tl < 64; tl++){
            float a = sdA[tl], d = sdt[tl];
            float x = sX[tl][p];
            float dx = d * x;
            float bb[16], cc[16];
            #pragma unroll
            for (int q = 0; q < 4; q++){
                *(float4*)&bb[q*4] = *(const float4*)&sB[tl][q*4];
                *(float4*)&cc[q*4] = *(const float4*)&sC[tl][q*4];
            }
            float acc = 0.f;
            #pragma unroll
            for (int j = 0; j < 16; j++){
                hreg[j] = hreg[j]*a + dx*bb[j];
                acc = fmaf(hreg[j], cc[j], acc);
            }
            int grow = base + (dir ? (Lsz-1 - (t0+tl)) : (t0+tl));
            yp[(size_t)grow*DI + h*HD + p] = fmaf(Dh, x, acc);
        }
        __syncthreads();
    }
}

// ---------------- gated RMSNorm (1024 dims): g = rms(y*silu(z)) * w ---------
__global__ void gnorm_k(const float* __restrict__ mnw)
{
    const int row = blockIdx.x, dir = blockIdx.y;
    const int tid = threadIdx.x;  // 256 threads x float4 = 1024
    const float4 yv = ((const float4*)(g_y[dir] + (size_t)row*DI))[tid];
    const float4 zv = *(const float4*)(g_zx[dir] + (size_t)row*DPROJ + tid*4);
    float4 v;
    v.x = yv.x * siluf(zv.x);
    v.y = yv.y * siluf(zv.y);
    v.z = yv.z * siluf(zv.z);
    v.w = yv.w * siluf(zv.w);
    float ss = v.x*v.x + v.y*v.y + v.z*v.z + v.w*v.w;
    #pragma unroll
    for (int o = 16; o > 0; o >>= 1) ss += __shfl_xor_sync(0xffffffffu, ss, o);
    __shared__ float ws[8];
    if ((tid & 31) == 0) ws[tid >> 5] = ss;
    __syncthreads();
    float tot = 0.f;
    #pragma unroll
    for (int i = 0; i < 8; i++) tot += ws[i];
    float inv = rsqrtf(tot * (1.0f/DI) + 1e-5f);
    const float4 wv = *(const float4*)(mnw + dir*DI + tid*4);
    float4 o4;
    o4.x = v.x*inv*wv.x; o4.y = v.y*inv*wv.y;
    o4.z = v.z*inv*wv.z; o4.w = v.w*inv*wv.w;
    *(float4*)&g_gbuf[(size_t)row*(2*DI) + dir*DI + tid*4] = o4;
}

// ---------------- launch ----------------
extern "C" void kernel_launch(void* const* d_in, const int* in_sizes, int n_in,
                              void* d_out, int out_size)
{
    const float* x      = (const float*)d_in[0];
    const float* pos    = (const float*)d_in[1];
    const float* mask   = (const float*)d_in[2];
    const float* W_in   = (const float*)d_in[3];
    const float* conv_w = (const float*)d_in[4];
    const float* conv_b = (const float*)d_in[5];
    const float* A_log  = (const float*)d_in[6];
    const float* Dvec   = (const float*)d_in[7];
    const float* dt_b   = (const float*)d_in[8];
    const float* mnw    = (const float*)d_in[9];
    const float* W_out  = (const float*)d_in[10];
    const float* nssm   = (const float*)d_in[11];
    const float* fw1    = (const float*)d_in[12];
    const float* fb1    = (const float*)d_in[13];
    const float* fw2    = (const float*)d_in[14];
    const float* fb2    = (const float*)d_in[15];
    const float* nffn   = (const float*)d_in[16];
    const float* fnw    = (const float*)d_in[17];

    float *xbuf, *s, *zx, *gbuf, *ffnh;
    cudaGetSymbolAddress((void**)&xbuf, g_xbuf);
    cudaGetSymbolAddress((void**)&s,    g_s);
    cudaGetSymbolAddress((void**)&zx,   g_zx);
    cudaGetSymbolAddress((void**)&gbuf, g_gbuf);
    cudaGetSymbolAddress((void**)&ffnh, g_ffnh);

    copy_k<<<(ROWS*DM + 255)/256, 256>>>(x, xbuf, ROWS*DM);

    for (int l = 0; l < NL; l++){
        // s = (rms(x, nssm) + pos) * mask
        rms512_k<<<ROWS, 128>>>(xbuf, nssm + l*DM, pos, mask, s, 1e-6f);
        // zx[dir] = s @ W_in[l,dir]   (both dirs via grid.z)
        sgemm_k<0><<<dim3(17, 16, 2), 256>>>(
            s, W_in + (size_t)l*2*DM*DPROJ, zx, ROWS, DPROJ, DM,
            nullptr, nullptr, 0.f, (long)DM*DPROJ, (long)ROWS*DPROJ);
        // conv + silu (both dirs)
        conv_k<<<dim3((ROWS*CONVD + 255)/256, 2), 256>>>(
            conv_w + (size_t)l*2*CONVD*4, conv_b + (size_t)l*2*CONVD);
        // dt / dA
        dt_k<<<dim3((ROWS*NH + 255)/256, 2), 256>>>(
            dt_b + (size_t)l*2*NH, A_log + (size_t)l*2*NH);
        // selective scan (64 chains)
        scan_k<<<64, 64>>>(Dvec + (size_t)l*2*NH);
        // gated norm -> concatenated g
        gnorm_k<<<dim3(ROWS, 2), 256>>>(mnw + (size_t)l*2*DI);
        // x += 0.5*mask*(g @ [W_out_f; W_out_b])
        sgemm_k<3><<<dim3(4, 16, 1), 256>>>(
            gbuf, W_out + (size_t)l*2*DI*DM, xbuf, ROWS, DM, 2*DI,
            nullptr, mask, 0.5f, 0, 0);
        // FFN
        rms512_k<<<ROWS, 128>>>(xbuf, nffn + l*DM, nullptr, nullptr, s, 1e-6f);
        sgemm_k<1><<<dim3(16, 16, 1), 256>>>(
            s, fw1 + (size_t)l*DM*FFND, ffnh, ROWS, FFND, DM,
            fb1 + (size_t)l*FFND, nullptr, 0.f, 0, 0);
        sgemm_k<2><<<dim3(4, 16, 1), 256>>>(
            ffnh, fw2 + (size_t)l*FFND*DM, xbuf, ROWS, DM, FFND,
            fb2 + (size_t)l*DM, nullptr, 0.f, 0, 0);
    }

    rms512_k<<<ROWS, 128>>>(xbuf, fnw, nullptr, nullptr, (float*)d_out, 1e-6f);
}

// round 5
// speedup vs baseline: 1.1612x; 1.1612x over previous
#include <cuda_runtime.h>
#include <math.h>

#define Bsz 2
#define Lsz 1024
#define DM 512
#define DSTATE 16
#define HD 64
#define DI 1024
#define NH 16
#define NL 6
#define FFND 2048
#define CONVD 1056
#define DPROJ 2096
#define ROWS (Bsz*Lsz)   // 2048

typedef unsigned long long ull;

// ---------------- scratch (static __device__, no allocation) ----------------
__device__ float g_xbuf[ROWS*DM];
__device__ float g_s[ROWS*DM];
__device__ float g_zx[2][ROWS*DPROJ];
__device__ float g_xconv[2][ROWS*CONVD];
__device__ float g_dt[2][ROWS*NH];
__device__ float g_dA[2][ROWS*NH];
__device__ float g_y[2][ROWS*DI];
__device__ float g_gbuf[ROWS*2*DI];
__device__ float g_ffnh[ROWS*FFND];

__device__ __forceinline__ float siluf(float x){ return x / (1.0f + expf(-x)); }
__device__ __forceinline__ float gelunf(float x){ return 0.5f*x*(1.0f+erff(x*0.70710678118654752f)); }

__device__ __forceinline__ ull pack2(float a, float b){
    ull r; asm("mov.b64 %0, {%1, %2};" : "=l"(r) : "f"(a), "f"(b)); return r;
}
__device__ __forceinline__ void ffma2(ull &d, ull a, ull b){
    asm("fma.rn.f32x2 %0, %1, %2, %0;" : "+l"(d) : "l"(a), "l"(b));
}
__device__ __forceinline__ float2 unpack2(ull v){
    float2 r; asm("mov.b64 {%0, %1}, %2;" : "=f"(r.x), "=f"(r.y) : "l"(v)); return r;
}

// ---------------- simple copy ----------------
__global__ void copy_k(const float* __restrict__ in, float* __restrict__ out, int n){
    int i = blockIdx.x*blockDim.x + threadIdx.x;
    if (i < n) out[i] = in[i];
}

// ---------------- RMSNorm over 512 dims; optional (+pos)*mask ----------------
__global__ void rms512_k(const float* __restrict__ in, const float* __restrict__ w,
                         const float* __restrict__ pos, const float* __restrict__ mask,
                         float* __restrict__ out, float eps)
{
    int row = blockIdx.x;
    int tid = threadIdx.x;  // 128 threads, float4 each = 512
    const float4 v = ((const float4*)(in + (size_t)row*DM))[tid];
    float ss = v.x*v.x + v.y*v.y + v.z*v.z + v.w*v.w;
    #pragma unroll
    for (int o = 16; o > 0; o >>= 1) ss += __shfl_xor_sync(0xffffffffu, ss, o);
    __shared__ float ws[4];
    if ((tid & 31) == 0) ws[tid >> 5] = ss;
    __syncthreads();
    float tot = ws[0] + ws[1] + ws[2] + ws[3];
    float inv = rsqrtf(tot * (1.0f/DM) + eps);
    const float4 wv = ((const float4*)w)[tid];
    float4 o4;
    o4.x = v.x*inv*wv.x; o4.y = v.y*inv*wv.y; o4.z = v.z*inv*wv.z; o4.w = v.w*inv*wv.w;
    if (pos){
        float m = mask[row];
        const float4 p4 = ((const float4*)(pos + (size_t)row*DM))[tid];
        o4.x = (o4.x + p4.x)*m; o4.y = (o4.y + p4.y)*m;
        o4.z = (o4.z + p4.z)*m; o4.w = (o4.w + p4.w)*m;
    }
    ((float4*)(out + (size_t)row*DM))[tid] = o4;
}

// ---------------- SGEMM BMx128x8, 256 thr, f32x2 packed FMA, double-buffered
// EPI 0: C = acc
// EPI 1: C = gelu(acc + bias[col])
// EPI 2: C = C + acc + bias[col]          (ffn2 residual, in-place)
// EPI 3: C += scale * extra[row] * acc    (out-proj combine into residual)
template<int EPI, int BM>
__global__ __launch_bounds__(256)
void sgemm_k(const float* __restrict__ A, const float* __restrict__ B,
             float* __restrict__ C, int M, int N, int K,
             const float* __restrict__ bias, const float* __restrict__ extra,
             float scale, long strideB, long strideC)
{
    constexpr int TM = BM/16;          // 8 (BM=128) or 4 (BM=64)
    constexpr int AV = BM/32;          // floats per thread per k-slab for A
    B += (size_t)blockIdx.z * strideB;
    C += (size_t)blockIdx.z * strideC;
    __shared__ __align__(16) float As[2][8][BM];
    __shared__ __align__(16) float Bs[2][8][128];
    const int tid = threadIdx.x;
    const int bx = blockIdx.x, by = blockIdx.y;

    int arow, acol;
    if (BM == 128){ arow = tid >> 1; acol = (tid & 1)*4; }
    else          { arow = tid >> 2; acol = (tid & 3)*2; }
    const int brow = tid >> 5, bcol = (tid & 31)*4;
    const int gcolB = bx*128 + bcol;
    const float* Aptr = A + (size_t)(by*BM + arow)*K + acol;
    const float* Bptr = B + (size_t)brow*N + gcolB;
    const bool bok = (gcolB < N);

    ull acc2[TM][4];
    #pragma unroll
    for (int i = 0; i < TM; i++)
        #pragma unroll
        for (int jp = 0; jp < 4; jp++) acc2[i][jp] = 0ull;

    const int ty = tid >> 4, tx = tid & 15;

    float av[4];
    float4 bv;
    // preload first k-slab
    if (BM == 128){
        float4 t = *(const float4*)Aptr;
        av[0]=t.x; av[1]=t.y; av[2]=t.z; av[3]=t.w;
    } else {
        float2 t = *(const float2*)Aptr;
        av[0]=t.x; av[1]=t.y;
    }
    bv = bok ? *(const float4*)Bptr : make_float4(0.f,0.f,0.f,0.f);
    Aptr += 8; Bptr += (size_t)8*N;
    #pragma unroll
    for (int q = 0; q < AV; q++) As[0][acol+q][arow] = av[q];
    *(float4*)&Bs[0][brow][bcol] = bv;
    __syncthreads();

    int buf = 0;
    for (int k0 = 8; k0 <= K; k0 += 8){
        const bool has = (k0 < K);
        if (has){
            if (BM == 128){
                float4 t = *(const float4*)Aptr;
                av[0]=t.x; av[1]=t.y; av[2]=t.z; av[3]=t.w;
            } else {
                float2 t = *(const float2*)Aptr;
                av[0]=t.x; av[1]=t.y;
            }
            bv = bok ? *(const float4*)Bptr : make_float4(0.f,0.f,0.f,0.f);
            Aptr += 8; Bptr += (size_t)8*N;
        }
        #pragma unroll
        for (int kk = 0; kk < 8; kk++){
            float ra[TM];
            if (BM == 128){
                *(float4*)&ra[0] = *(const float4*)&As[buf][kk][ty*8];
                *(float4*)&ra[4] = *(const float4*)&As[buf][kk][ty*8+4];
            } else {
                *(float4*)&ra[0] = *(const float4*)&As[buf][kk][ty*4];
            }
            ulonglong2 q0 = *(const ulonglong2*)&Bs[buf][kk][tx*8];
            ulonglong2 q1 = *(const ulonglong2*)&Bs[buf][kk][tx*8+4];
            ull rb2[4]; rb2[0]=q0.x; rb2[1]=q0.y; rb2[2]=q1.x; rb2[3]=q1.y;
            #pragma unroll
            for (int i = 0; i < TM; i++){
                ull ar = pack2(ra[i], ra[i]);
                #pragma unroll
                for (int jp = 0; jp < 4; jp++) ffma2(acc2[i][jp], ar, rb2[jp]);
            }
        }
        if (has){
            #pragma unroll
            for (int q = 0; q < AV; q++) As[buf^1][acol+q][arow] = av[q];
            *(float4*)&Bs[buf^1][brow][bcol] = bv;
            __syncthreads();
            buf ^= 1;
        }
    }

    const int row0 = by*BM + ty*TM, col0 = bx*128 + tx*8;
    #pragma unroll
    for (int i = 0; i < TM; i++){
        const size_t r = (size_t)(row0 + i);
        float m = 0.f;
        if (EPI == 3) m = scale * extra[r];
        #pragma unroll
        for (int jp = 0; jp < 4; jp++){
            float2 v = unpack2(acc2[i][jp]);
            const int c0 = col0 + jp*2;
            if (c0 < N){
                if (EPI == 0)      C[r*N + c0] = v.x;
                else if (EPI == 1) C[r*N + c0] = gelunf(v.x + bias[c0]);
                else if (EPI == 2) C[r*N + c0] = C[r*N + c0] + v.x + bias[c0];
                else               C[r*N + c0] = fmaf(m, v.x, C[r*N + c0]);
            }
            if (c0 + 1 < N){
                if (EPI == 0)      C[r*N + c0+1] = v.y;
                else if (EPI == 1) C[r*N + c0+1] = gelunf(v.y + bias[c0+1]);
                else if (EPI == 2) C[r*N + c0+1] = C[r*N + c0+1] + v.y + bias[c0+1];
                else               C[r*N + c0+1] = fmaf(m, v.y, C[r*N + c0+1]);
            }
        }
    }
}

// ---------------- causal depthwise conv (dir-aware) + SiLU ----------------
__global__ void conv_k(const float* __restrict__ cw, const float* __restrict__ cb)
{
    const int dir = blockIdx.y;
    const int idx = blockIdx.x*blockDim.x + threadIdx.x;
    if (idx >= ROWS*CONVD) return;
    const int row = idx / CONVD, c = idx - row*CONVD;
    const int b = row >> 10, l = row & 1023;
    const float* zx = g_zx[dir];
    const float* w = cw + (size_t)dir*CONVD*4 + (size_t)c*4;
    float acc = cb[dir*CONVD + c];
    #pragma unroll
    for (int k = 0; k < 4; k++){
        int lp = dir ? (l + 3 - k) : (l - 3 + k);
        if (lp >= 0 && lp < Lsz)
            acc = fmaf(w[k], zx[(size_t)(b*Lsz + lp)*DPROJ + DI + c], acc);
    }
    g_xconv[dir][idx] = siluf(acc);
}

// ---------------- dt = softplus(raw + bias); dA = exp(dt * -exp(A_log)) ----
__global__ void dt_k(const float* __restrict__ dtb, const float* __restrict__ Alog)
{
    const int dir = blockIdx.y;
    const int idx = blockIdx.x*blockDim.x + threadIdx.x;
    if (idx >= ROWS*NH) return;
    const int row = idx >> 4, h = idx & 15;
    float raw = g_zx[dir][(size_t)row*DPROJ + DI + CONVD + h] + dtb[dir*NH + h];
    float dt = (raw > 20.f) ? raw : log1pf(expf(raw));
    float A = -expf(Alog[dir*NH + h]);
    g_dt[dir][idx] = dt;
    g_dA[dir][idx] = expf(dt * A);
}

// ---------------- selective scan: block per (dir,b,head), thread per p ------
__global__ __launch_bounds__(64)
void scan_k(const float* __restrict__ Dvec)
{
    const int blk = blockIdx.x;
    const int dir = blk >> 5, b = (blk >> 4) & 1, h = blk & 15;
    const float* xc  = g_xconv[dir];
    const float* dtp = g_dt[dir];
    const float* dAp = g_dA[dir];
    float* yp = g_y[dir];
    const float Dh = Dvec[dir*NH + h];
    const int p = threadIdx.x;
    const int base = b*Lsz;

    __shared__ float sX[64][64];
    __shared__ float sB[64][16], sC[64][16];
    __shared__ float sdA[64], sdt[64];

    float hreg[16];
    #pragma unroll
    for (int j = 0; j < 16; j++) hreg[j] = 0.f;

    for (int t0 = 0; t0 < Lsz; t0 += 64){
        #pragma unroll
        for (int i = 0; i < 16; i++){
            int li = p + i*64;
            int tl = li >> 4, pq = li & 15;
            int grow = base + (dir ? (Lsz-1 - (t0+tl)) : (t0+tl));
            *(float4*)&sX[tl][pq*4] =
                *(const float4*)&xc[(size_t)grow*CONVD + h*HD + pq*4];
        }
        #pragma unroll
        for (int i = 0; i < 4; i++){
            int li = p + i*64;
            int tl = li >> 2, j4 = (li & 3)*4;
            int grow = base + (dir ? (Lsz-1 - (t0+tl)) : (t0+tl));
            *(float4*)&sB[tl][j4] = *(const float4*)&xc[(size_t)grow*CONVD + DI + j4];
            *(float4*)&sC[tl][j4] = *(const float4*)&xc[(size_t)grow*CONVD + DI + DSTATE + j4];
        }
        {
            int grow = base + (dir ? (Lsz-1 - (t0+p)) : (t0+p));
            sdA[p] = dAp[grow*NH + h];
            sdt[p] = dtp[grow*NH + h];
        }
        __syncthreads();

        for (int tl = 0; tl < 64; tl++){
            float a = sdA[tl], d = sdt[tl];
            float x = sX[tl][p];
            float dx = d * x;
            float bb[16], cc[16];
            #pragma unroll
            for (int q = 0; q < 4; q++){
                *(float4*)&bb[q*4] = *(const float4*)&sB[tl][q*4];
                *(float4*)&cc[q*4] = *(const float4*)&sC[tl][q*4];
            }
            float acc = 0.f;
            #pragma unroll
            for (int j = 0; j < 16; j++){
                hreg[j] = hreg[j]*a + dx*bb[j];
                acc = fmaf(hreg[j], cc[j], acc);
            }
            int grow = base + (dir ? (Lsz-1 - (t0+tl)) : (t0+tl));
            yp[(size_t)grow*DI + h*HD + p] = fmaf(Dh, x, acc);
        }
        __syncthreads();
    }
}

// ---------------- gated RMSNorm (1024 dims): g = rms(y*silu(z)) * w ---------
__global__ void gnorm_k(const float* __restrict__ mnw)
{
    const int row = blockIdx.x, dir = blockIdx.y;
    const int tid = threadIdx.x;  // 256 threads x float4 = 1024
    const float4 yv = ((const float4*)(g_y[dir] + (size_t)row*DI))[tid];
    const float4 zv = *(const float4*)(g_zx[dir] + (size_t)row*DPROJ + tid*4);
    float4 v;
    v.x = yv.x * siluf(zv.x);
    v.y = yv.y * siluf(zv.y);
    v.z = yv.z * siluf(zv.z);
    v.w = yv.w * siluf(zv.w);
    float ss = v.x*v.x + v.y*v.y + v.z*v.z + v.w*v.w;
    #pragma unroll
    for (int o = 16; o > 0; o >>= 1) ss += __shfl_xor_sync(0xffffffffu, ss, o);
    __shared__ float ws[8];
    if ((tid & 31) == 0) ws[tid >> 5] = ss;
    __syncthreads();
    float tot = 0.f;
    #pragma unroll
    for (int i = 0; i < 8; i++) tot += ws[i];
    float inv = rsqrtf(tot * (1.0f/DI) + 1e-5f);
    const float4 wv = *(const float4*)(mnw + dir*DI + tid*4);
    float4 o4;
    o4.x = v.x*inv*wv.x; o4.y = v.y*inv*wv.y;
    o4.z = v.z*inv*wv.z; o4.w = v.w*inv*wv.w;
    *(float4*)&g_gbuf[(size_t)row*(2*DI) + dir*DI + tid*4] = o4;
}

// ---------------- launch ----------------
extern "C" void kernel_launch(void* const* d_in, const int* in_sizes, int n_in,
                              void* d_out, int out_size)
{
    const float* x      = (const float*)d_in[0];
    const float* pos    = (const float*)d_in[1];
    const float* mask   = (const float*)d_in[2];
    const float* W_in   = (const float*)d_in[3];
    const float* conv_w = (const float*)d_in[4];
    const float* conv_b = (const float*)d_in[5];
    const float* A_log  = (const float*)d_in[6];
    const float* Dvec   = (const float*)d_in[7];
    const float* dt_b   = (const float*)d_in[8];
    const float* mnw    = (const float*)d_in[9];
    const float* W_out  = (const float*)d_in[10];
    const float* nssm   = (const float*)d_in[11];
    const float* fw1    = (const float*)d_in[12];
    const float* fb1    = (const float*)d_in[13];
    const float* fw2    = (const float*)d_in[14];
    const float* fb2    = (const float*)d_in[15];
    const float* nffn   = (const float*)d_in[16];
    const float* fnw    = (const float*)d_in[17];

    float *xbuf, *s, *zx, *gbuf, *ffnh;
    cudaGetSymbolAddress((void**)&xbuf, g_xbuf);
    cudaGetSymbolAddress((void**)&s,    g_s);
    cudaGetSymbolAddress((void**)&zx,   g_zx);
    cudaGetSymbolAddress((void**)&gbuf, g_gbuf);
    cudaGetSymbolAddress((void**)&ffnh, g_ffnh);

    copy_k<<<(ROWS*DM + 255)/256, 256>>>(x, xbuf, ROWS*DM);

    for (int l = 0; l < NL; l++){
        // s = (rms(x, nssm) + pos) * mask
        rms512_k<<<ROWS, 128>>>(xbuf, nssm + l*DM, pos, mask, s, 1e-6f);
        // zx[dir] = s @ W_in[l,dir]
        sgemm_k<0,128><<<dim3(17, 16, 2), 256>>>(
            s, W_in + (size_t)l*2*DM*DPROJ, zx, ROWS, DPROJ, DM,
            nullptr, nullptr, 0.f, (long)DM*DPROJ, (long)ROWS*DPROJ);
        // conv + silu (both dirs)
        conv_k<<<dim3((ROWS*CONVD + 255)/256, 2), 256>>>(
            conv_w + (size_t)l*2*CONVD*4, conv_b + (size_t)l*2*CONVD);
        // dt / dA
        dt_k<<<dim3((ROWS*NH + 255)/256, 2), 256>>>(
            dt_b + (size_t)l*2*NH, A_log + (size_t)l*2*NH);
        // selective scan (64 chains)
        scan_k<<<64, 64>>>(Dvec + (size_t)l*2*NH);
        // gated norm -> concatenated g
        gnorm_k<<<dim3(ROWS, 2), 256>>>(mnw + (size_t)l*2*DI);
        // x += 0.5*mask*(g @ [W_out_f; W_out_b])   (BM=64: 128 CTAs)
        sgemm_k<3,64><<<dim3(4, 32, 1), 256>>>(
            gbuf, W_out + (size_t)l*2*DI*DM, xbuf, ROWS, DM, 2*DI,
            nullptr, mask, 0.5f, 0, 0);
        // FFN
        rms512_k<<<ROWS, 128>>>(xbuf, nffn + l*DM, nullptr, nullptr, s, 1e-6f);
        sgemm_k<1,128><<<dim3(16, 16, 1), 256>>>(
            s, fw1 + (size_t)l*DM*FFND, ffnh, ROWS, FFND, DM,
            fb1 + (size_t)l*FFND, nullptr, 0.f, 0, 0);
        sgemm_k<2,64><<<dim3(4, 32, 1), 256>>>(
            ffnh, fw2 + (size_t)l*FFND*DM, xbuf, ROWS, DM, FFND,
            fb2 + (size_t)l*DM, nullptr, 0.f, 0, 0);
    }

    rms512_k<<<ROWS, 128>>>(xbuf, fnw, nullptr, nullptr, (float*)d_out, 1e-6f);
}

// round 9
// speedup vs baseline: 1.3342x; 1.1489x over previous
#include <cuda_runtime.h>
#include <math.h>

#define Bsz 2
#define Lsz 1024
#define DM 512
#define DSTATE 16
#define HD 64
#define DI 1024
#define NH 16
#define NL 6
#define FFND 2048
#define CONVD 1056
#define DPROJ 2096
#define ROWS (Bsz*Lsz)   // 2048

typedef unsigned long long ull;

// ---------------- scratch (static __device__, no allocation) ----------------
__device__ float g_xbuf[ROWS*DM];
__device__ float g_s[ROWS*DM];
__device__ float g_zx[2][ROWS*DPROJ];
__device__ float g_xconv[2][ROWS*CONVD];
__device__ float g_dt[2][ROWS*NH];
__device__ float g_dA[2][ROWS*NH];
__device__ float g_y[2][ROWS*DI];
__device__ float g_gbuf[ROWS*2*DI];
__device__ float g_ffnh[ROWS*FFND];

__device__ __forceinline__ float siluf(float x){ return x / (1.0f + expf(-x)); }
__device__ __forceinline__ float gelunf(float x){ return 0.5f*x*(1.0f+erff(x*0.70710678118654752f)); }

__device__ __forceinline__ ull pack2(float a, float b){
    ull r; asm("mov.b64 %0, {%1, %2};" : "=l"(r) : "f"(a), "f"(b)); return r;
}
__device__ __forceinline__ void ffma2(ull &d, ull a, ull b){
    asm("fma.rn.f32x2 %0, %1, %2, %0;" : "+l"(d) : "l"(a), "l"(b));
}
__device__ __forceinline__ float2 unpack2(ull v){
    float2 r; asm("mov.b64 {%0, %1}, %2;" : "=f"(r.x), "=f"(r.y) : "l"(v)); return r;
}

// ---------------- simple copy ----------------
__global__ void copy_k(const float* __restrict__ in, float* __restrict__ out, int n){
    int i = blockIdx.x*blockDim.x + threadIdx.x;
    if (i < n) out[i] = in[i];
}

// ---------------- RMSNorm over 512 dims; optional (+pos)*mask ----------------
__global__ void rms512_k(const float* __restrict__ in, const float* __restrict__ w,
                         const float* __restrict__ pos, const float* __restrict__ mask,
                         float* __restrict__ out, float eps)
{
    int row = blockIdx.x;
    int tid = threadIdx.x;  // 128 threads, float4 each = 512
    const float4 v = ((const float4*)(in + (size_t)row*DM))[tid];
    float ss = v.x*v.x + v.y*v.y + v.z*v.z + v.w*v.w;
    #pragma unroll
    for (int o = 16; o > 0; o >>= 1) ss += __shfl_xor_sync(0xffffffffu, ss, o);
    __shared__ float ws[4];
    if ((tid & 31) == 0) ws[tid >> 5] = ss;
    __syncthreads();
    float tot = ws[0] + ws[1] + ws[2] + ws[3];
    float inv = rsqrtf(tot * (1.0f/DM) + eps);
    const float4 wv = ((const float4*)w)[tid];
    float4 o4;
    o4.x = v.x*inv*wv.x; o4.y = v.y*inv*wv.y; o4.z = v.z*inv*wv.z; o4.w = v.w*inv*wv.w;
    if (pos){
        float m = mask[row];
        const float4 p4 = ((const float4*)(pos + (size_t)row*DM))[tid];
        o4.x = (o4.x + p4.x)*m; o4.y = (o4.y + p4.y)*m;
        o4.z = (o4.z + p4.z)*m; o4.w = (o4.w + p4.w)*m;
    }
    ((float4*)(out + (size_t)row*DM))[tid] = o4;
}

// ---------------- SGEMM BMx128x8, 256 thr, f32x2 packed FMA, double-buffered
// B-fragment is split: cols [tx*4, tx*4+4) and [64+tx*4, 64+tx*4+4)
// -> LDS.128 at 16B lane stride = conflict-free.
// EPI 0: C = acc
// EPI 1: C = gelu(acc + bias[col])
// EPI 2: C = C + acc + bias[col]          (ffn2 residual, in-place)
// EPI 3: C += scale * extra[row] * acc    (out-proj combine into residual)
template<int EPI, int BM>
__global__ __launch_bounds__(256)
void sgemm_k(const float* __restrict__ A, const float* __restrict__ B,
             float* __restrict__ C, int M, int N, int K,
             const float* __restrict__ bias, const float* __restrict__ extra,
             float scale, long strideB, long strideC)
{
    constexpr int TM = BM/16;          // 8 (BM=128) or 4 (BM=64)
    constexpr int AV = BM/32;          // floats per thread per k-slab for A
    B += (size_t)blockIdx.z * strideB;
    C += (size_t)blockIdx.z * strideC;
    __shared__ __align__(16) float As[2][8][BM];
    __shared__ __align__(16) float Bs[2][8][128];
    const int tid = threadIdx.x;
    const int bx = blockIdx.x, by = blockIdx.y;

    int arow, acol;
    if (BM == 128){ arow = tid >> 1; acol = (tid & 1)*4; }
    else          { arow = tid >> 2; acol = (tid & 3)*2; }
    const int brow = tid >> 5, bcol = (tid & 31)*4;
    const int gcolB = bx*128 + bcol;
    const float* Aptr = A + (size_t)(by*BM + arow)*K + acol;
    const float* Bptr = B + (size_t)brow*N + gcolB;
    const bool bok = (gcolB < N);

    ull acc2[TM][4];
    #pragma unroll
    for (int i = 0; i < TM; i++)
        #pragma unroll
        for (int jp = 0; jp < 4; jp++) acc2[i][jp] = 0ull;

    const int ty = tid >> 4, tx = tid & 15;

    float av[4];
    float4 bv;
    // preload first k-slab
    if (BM == 128){
        float4 t = *(const float4*)Aptr;
        av[0]=t.x; av[1]=t.y; av[2]=t.z; av[3]=t.w;
    } else {
        float2 t = *(const float2*)Aptr;
        av[0]=t.x; av[1]=t.y;
    }
    bv = bok ? *(const float4*)Bptr : make_float4(0.f,0.f,0.f,0.f);
    Aptr += 8; Bptr += (size_t)8*N;
    #pragma unroll
    for (int q = 0; q < AV; q++) As[0][acol+q][arow] = av[q];
    *(float4*)&Bs[0][brow][bcol] = bv;
    __syncthreads();

    int buf = 0;
    for (int k0 = 8; k0 <= K; k0 += 8){
        const bool has = (k0 < K);
        if (has){
            if (BM == 128){
                float4 t = *(const float4*)Aptr;
                av[0]=t.x; av[1]=t.y; av[2]=t.z; av[3]=t.w;
            } else {
                float2 t = *(const float2*)Aptr;
                av[0]=t.x; av[1]=t.y;
            }
            bv = bok ? *(const float4*)Bptr : make_float4(0.f,0.f,0.f,0.f);
            Aptr += 8; Bptr += (size_t)8*N;
        }
        #pragma unroll
        for (int kk = 0; kk < 8; kk++){
            float ra[TM];
            if (BM == 128){
                *(float4*)&ra[0] = *(const float4*)&As[buf][kk][ty*8];
                *(float4*)&ra[4] = *(const float4*)&As[buf][kk][ty*8+4];
            } else {
                *(float4*)&ra[0] = *(const float4*)&As[buf][kk][ty*4];
            }
            // conflict-free: lane stride 16B
            ulonglong2 q0 = *(const ulonglong2*)&Bs[buf][kk][tx*4];
            ulonglong2 q1 = *(const ulonglong2*)&Bs[buf][kk][64 + tx*4];
            ull rb2[4]; rb2[0]=q0.x; rb2[1]=q0.y; rb2[2]=q1.x; rb2[3]=q1.y;
            #pragma unroll
            for (int i = 0; i < TM; i++){
                ull ar = pack2(ra[i], ra[i]);
                #pragma unroll
                for (int jp = 0; jp < 4; jp++) ffma2(acc2[i][jp], ar, rb2[jp]);
            }
        }
        if (has){
            #pragma unroll
            for (int q = 0; q < AV; q++) As[buf^1][acol+q][arow] = av[q];
            *(float4*)&Bs[buf^1][brow][bcol] = bv;
            __syncthreads();
            buf ^= 1;
        }
    }

    const int row0 = by*BM + ty*TM;
    const int cA = bx*128 + tx*4;      // fragment 0: 4 cols
    const int cB = cA + 64;            // fragment 1: 4 cols
    #pragma unroll
    for (int i = 0; i < TM; i++){
        const size_t r = (size_t)(row0 + i);
        float m = 0.f;
        if (EPI == 3) m = scale * extra[r];
        #pragma unroll
        for (int jp = 0; jp < 4; jp++){
            float2 v = unpack2(acc2[i][jp]);
            const int c0 = (jp < 2) ? (cA + jp*2) : (cB + (jp-2)*2);
            if (c0 < N){
                if (EPI == 0)      C[r*N + c0] = v.x;
                else if (EPI == 1) C[r*N + c0] = gelunf(v.x + bias[c0]);
                else if (EPI == 2) C[r*N + c0] = C[r*N + c0] + v.x + bias[c0];
                else               C[r*N + c0] = fmaf(m, v.x, C[r*N + c0]);
            }
            if (c0 + 1 < N){
                if (EPI == 0)      C[r*N + c0+1] = v.y;
                else if (EPI == 1) C[r*N + c0+1] = gelunf(v.y + bias[c0+1]);
                else if (EPI == 2) C[r*N + c0+1] = C[r*N + c0+1] + v.y + bias[c0+1];
                else               C[r*N + c0+1] = fmaf(m, v.y, C[r*N + c0+1]);
            }
        }
    }
}

// ---------------- causal depthwise conv (dir-aware) + SiLU ----------------
__global__ void conv_k(const float* __restrict__ cw, const float* __restrict__ cb)
{
    const int dir = blockIdx.y;
    const int idx = blockIdx.x*blockDim.x + threadIdx.x;
    if (idx >= ROWS*CONVD) return;
    const int row = idx / CONVD, c = idx - row*CONVD;
    const int b = row >> 10, l = row & 1023;
    const float* zx = g_zx[dir];
    const float* w = cw + (size_t)dir*CONVD*4 + (size_t)c*4;
    float acc = cb[dir*CONVD + c];
    #pragma unroll
    for (int k = 0; k < 4; k++){
        int lp = dir ? (l + 3 - k) : (l - 3 + k);
        if (lp >= 0 && lp < Lsz)
            acc = fmaf(w[k], zx[(size_t)(b*Lsz + lp)*DPROJ + DI + c], acc);
    }
    g_xconv[dir][idx] = siluf(acc);
}

// ---------------- dt = softplus(raw + bias); dA = exp(dt * -exp(A_log)) ----
__global__ void dt_k(const float* __restrict__ dtb, const float* __restrict__ Alog)
{
    const int dir = blockIdx.y;
    const int idx = blockIdx.x*blockDim.x + threadIdx.x;
    if (idx >= ROWS*NH) return;
    const int row = idx >> 4, h = idx & 15;
    float raw = g_zx[dir][(size_t)row*DPROJ + DI + CONVD + h] + dtb[dir*NH + h];
    float dt = (raw > 20.f) ? raw : log1pf(expf(raw));
    float A = -expf(Alog[dir*NH + h]);
    g_dt[dir][idx] = dt;
    g_dA[dir][idx] = expf(dt * A);
}

// ---------------- selective scan: block per (dir,b,head), thread per p ------
__global__ __launch_bounds__(64)
void scan_k(const float* __restrict__ Dvec)
{
    const int blk = blockIdx.x;
    const int dir = blk >> 5, b = (blk >> 4) & 1, h = blk & 15;
    const float* xc  = g_xconv[dir];
    const float* dtp = g_dt[dir];
    const float* dAp = g_dA[dir];
    float* yp = g_y[dir];
    const float Dh = Dvec[dir*NH + h];
    const int p = threadIdx.x;
    const int base = b*Lsz;

    __shared__ float sX[64][64];
    __shared__ float sB[64][16], sC[64][16];
    __shared__ float sdA[64], sdt[64];

    float hreg[16];
    #pragma unroll
    for (int j = 0; j < 16; j++) hreg[j] = 0.f;

    for (int t0 = 0; t0 < Lsz; t0 += 64){
        #pragma unroll
        for (int i = 0; i < 16; i++){
            int li = p + i*64;
            int tl = li >> 4, pq = li & 15;
            int grow = base + (dir ? (Lsz-1 - (t0+tl)) : (t0+tl));
            *(float4*)&sX[tl][pq*4] =
                *(const float4*)&xc[(size_t)grow*CONVD + h*HD + pq*4];
        }
        #pragma unroll
        for (int i = 0; i < 4; i++){
            int li = p + i*64;
            int tl = li >> 2, j4 = (li & 3)*4;
            int grow = base + (dir ? (Lsz-1 - (t0+tl)) : (t0+tl));
            *(float4*)&sB[tl][j4] = *(const float4*)&xc[(size_t)grow*CONVD + DI + j4];
            *(float4*)&sC[tl][j4] = *(const float4*)&xc[(size_t)grow*CONVD + DI + DSTATE + j4];
        }
        {
            int grow = base + (dir ? (Lsz-1 - (t0+p)) : (t0+p));
            sdA[p] = dAp[grow*NH + h];
            sdt[p] = dtp[grow*NH + h];
        }
        __syncthreads();

        for (int tl = 0; tl < 64; tl++){
            float a = sdA[tl], d = sdt[tl];
            float x = sX[tl][p];
            float dx = d * x;
            float bb[16], cc[16];
            #pragma unroll
            for (int q = 0; q < 4; q++){
                *(float4*)&bb[q*4] = *(const float4*)&sB[tl][q*4];
                *(float4*)&cc[q*4] = *(const float4*)&sC[tl][q*4];
            }
            float acc = 0.f;
            #pragma unroll
            for (int j = 0; j < 16; j++){
                hreg[j] = hreg[j]*a + dx*bb[j];
                acc = fmaf(hreg[j], cc[j], acc);
            }
            int grow = base + (dir ? (Lsz-1 - (t0+tl)) : (t0+tl));
            yp[(size_t)grow*DI + h*HD + p] = fmaf(Dh, x, acc);
        }
        __syncthreads();
    }
}

// ---------------- gated RMSNorm (1024 dims): g = rms(y*silu(z)) * w ---------
__global__ void gnorm_k(const float* __restrict__ mnw)
{
    const int row = blockIdx.x, dir = blockIdx.y;
    const int tid = threadIdx.x;  // 256 threads x float4 = 1024
    const float4 yv = ((const float4*)(g_y[dir] + (size_t)row*DI))[tid];
    const float4 zv = *(const float4*)(g_zx[dir] + (size_t)row*DPROJ + tid*4);
    float4 v;
    v.x = yv.x * siluf(zv.x);
    v.y = yv.y * siluf(zv.y);
    v.z = yv.z * siluf(zv.z);
    v.w = yv.w * siluf(zv.w);
    float ss = v.x*v.x + v.y*v.y + v.z*v.z + v.w*v.w;
    #pragma unroll
    for (int o = 16; o > 0; o >>= 1) ss += __shfl_xor_sync(0xffffffffu, ss, o);
    __shared__ float ws[8];
    if ((tid & 31) == 0) ws[tid >> 5] = ss;
    __syncthreads();
    float tot = 0.f;
    #pragma unroll
    for (int i = 0; i < 8; i++) tot += ws[i];
    float inv = rsqrtf(tot * (1.0f/DI) + 1e-5f);
    const float4 wv = *(const float4*)(mnw + dir*DI + tid*4);
    float4 o4;
    o4.x = v.x*inv*wv.x; o4.y = v.y*inv*wv.y;
    o4.z = v.z*inv*wv.z; o4.w = v.w*inv*wv.w;
    *(float4*)&g_gbuf[(size_t)row*(2*DI) + dir*DI + tid*4] = o4;
}

// ---------------- launch ----------------
extern "C" void kernel_launch(void* const* d_in, const int* in_sizes, int n_in,
                              void* d_out, int out_size)
{
    const float* x      = (const float*)d_in[0];
    const float* pos    = (const float*)d_in[1];
    const float* mask   = (const float*)d_in[2];
    const float* W_in   = (const float*)d_in[3];
    const float* conv_w = (const float*)d_in[4];
    const float* conv_b = (const float*)d_in[5];
    const float* A_log  = (const float*)d_in[6];
    const float* Dvec   = (const float*)d_in[7];
    const float* dt_b   = (const float*)d_in[8];
    const float* mnw    = (const float*)d_in[9];
    const float* W_out  = (const float*)d_in[10];
    const float* nssm   = (const float*)d_in[11];
    const float* fw1    = (const float*)d_in[12];
    const float* fb1    = (const float*)d_in[13];
    const float* fw2    = (const float*)d_in[14];
    const float* fb2    = (const float*)d_in[15];
    const float* nffn   = (const float*)d_in[16];
    const float* fnw    = (const float*)d_in[17];

    float *xbuf, *s, *zx, *gbuf, *ffnh;
    cudaGetSymbolAddress((void**)&xbuf, g_xbuf);
    cudaGetSymbolAddress((void**)&s,    g_s);
    cudaGetSymbolAddress((void**)&zx,   g_zx);
    cudaGetSymbolAddress((void**)&gbuf, g_gbuf);
    cudaGetSymbolAddress((void**)&ffnh, g_ffnh);

    copy_k<<<(ROWS*DM + 255)/256, 256>>>(x, xbuf, ROWS*DM);

    for (int l = 0; l < NL; l++){
        // s = (rms(x, nssm) + pos) * mask
        rms512_k<<<ROWS, 128>>>(xbuf, nssm + l*DM, pos, mask, s, 1e-6f);
        // zx[dir] = s @ W_in[l,dir]
        sgemm_k<0,128><<<dim3(17, 16, 2), 256>>>(
            s, W_in + (size_t)l*2*DM*DPROJ, zx, ROWS, DPROJ, DM,
            nullptr, nullptr, 0.f, (long)DM*DPROJ, (long)ROWS*DPROJ);
        // conv + silu (both dirs)
        conv_k<<<dim3((ROWS*CONVD + 255)/256, 2), 256>>>(
            conv_w + (size_t)l*2*CONVD*4, conv_b + (size_t)l*2*CONVD);
        // dt / dA
        dt_k<<<dim3((ROWS*NH + 255)/256, 2), 256>>>(
            dt_b + (size_t)l*2*NH, A_log + (size_t)l*2*NH);
        // selective scan (64 chains)
        scan_k<<<64, 64>>>(Dvec + (size_t)l*2*NH);
        // gated norm -> concatenated g
        gnorm_k<<<dim3(ROWS, 2), 256>>>(mnw + (size_t)l*2*DI);
        // x += 0.5*mask*(g @ [W_out_f; W_out_b])   (BM=64: 128 CTAs)
        sgemm_k<3,64><<<dim3(4, 32, 1), 256>>>(
            gbuf, W_out + (size_t)l*2*DI*DM, xbuf, ROWS, DM, 2*DI,
            nullptr, mask, 0.5f, 0, 0);
        // FFN
        rms512_k<<<ROWS, 128>>>(xbuf, nffn + l*DM, nullptr, nullptr, s, 1e-6f);
        sgemm_k<1,128><<<dim3(16, 16, 1), 256>>>(
            s, fw1 + (size_t)l*DM*FFND, ffnh, ROWS, FFND, DM,
            fb1 + (size_t)l*FFND, nullptr, 0.f, 0, 0);
        sgemm_k<2,64><<<dim3(4, 32, 1), 256>>>(
            ffnh, fw2 + (size_t)l*FFND*DM, xbuf, ROWS, DM, FFND,
            fb2 + (size_t)l*DM, nullptr, 0.f, 0, 0);
    }

    rms512_k<<<ROWS, 128>>>(xbuf, fnw, nullptr, nullptr, (float*)d_out, 1e-6f);
}